// round 14
// baseline (speedup 1.0000x reference)
#include <cuda_runtime.h>
#include <cuda_bf16.h>

#define B_    8
#define N_    2048
#define EMB_  256
#define KNN_  16
#define NPTS_ (B_*N_)

typedef unsigned long long ull;
typedef unsigned int u32;

// bf16 hi/lo split packers (lower col -> low 16 bits)
__device__ __forceinline__ u32 pack_hi(float v0, float v1) {
    __nv_bfloat162 h = __floats2bfloat162_rn(v0, v1);
    return *(u32*)&h;
}
__device__ __forceinline__ u32 pack_lo(float v0, float v1) {
    __nv_bfloat16 h0 = __float2bfloat16(v0), h1 = __float2bfloat16(v1);
    __nv_bfloat162 l = __floats2bfloat162_rn(v0 - __bfloat162float(h0),
                                             v1 - __bfloat162float(h1));
    return *(u32*)&l;
}

// m16n8k16 bf16 mma, f32 accum
__device__ __forceinline__ void mma_bf16(float d[4], const u32 a[4], u32 b0, u32 b1) {
    asm volatile("mma.sync.aligned.m16n8k16.row.col.f32.bf16.bf16.f32 "
        "{%0,%1,%2,%3}, {%4,%5,%6,%7}, {%8,%9}, {%0,%1,%2,%3};"
        : "+f"(d[0]), "+f"(d[1]), "+f"(d[2]), "+f"(d[3])
        : "r"(a[0]), "r"(a[1]), "r"(a[2]), "r"(a[3]), "r"(b0), "r"(b1));
}

// ---- Scratch (device globals) ----
__device__ float g_qmk[NPTS_*64];
__device__ float g_v  [NPTS_*64];
__device__ int   g_idx[NPTS_*KNN_];
// B-fragment-ordered weights, bf16 hi half then lo half:
__device__ __align__(16) u32 g_wqf[49152];        // w_qkv  [kt16][nt24][lane][b2] x2
__device__ __align__(16) u32 g_w1f[16384];        // w_att1 [kt4][nt32][lane][b2] x2
__device__ __align__(16) u32 g_w2f[16384];        // w_att2 [kt16][nt8][lane][b2] x2
__device__ __align__(16) u32 g_wpf[4096];         // w_pos2 [kt4][nt8][lane][b2] x2

// ---------------------------------------------------------------------------
__global__ __launch_bounds__(256) void prep_kernel(
    const float* __restrict__ wq, const float* __restrict__ w1,
    const float* __restrict__ w2, const float* __restrict__ wp)
{
    int i = blockIdx.x*256 + threadIdx.x;
    if (i < 49152) {
        int half = (i >= 24576);
        int j2 = half ? i - 24576 : i;
        int b = j2 & 1, lane = (j2 >> 1) & 31;
        int ktnt = j2 >> 6;            // 0..383
        int nt = ktnt % 24, kt = ktnt / 24;
        int tig = lane & 3, g = lane >> 2;
        int k0 = kt*16 + tig*2 + 8*b, n = nt*8 + g;
        float v0 = wq[k0*192 + n], v1 = wq[(k0+1)*192 + n];
        g_wqf[i] = half ? pack_lo(v0, v1) : pack_hi(v0, v1);
    } else if (i < 53248) {
        int j = i - 49152;               // wp2 frags, 4096 u32
        int half = j >> 11, j2 = j & 2047;
        int b = j2 & 1, lane = (j2 >> 1) & 31, nt = (j2 >> 6) & 7, kt = j2 >> 9;
        int tig = lane & 3, g = lane >> 2;
        int k0 = kt*16 + tig*2 + 8*b, n = nt*8 + g;
        float v0 = wp[k0*64 + n], v1 = wp[(k0+1)*64 + n];
        g_wpf[j] = half ? pack_lo(v0, v1) : pack_hi(v0, v1);
    } else if (i < 69632) {
        int j = i - 53248;               // w1 frags, 16384 u32
        int half = j >> 13, j2 = j & 8191;
        int b = j2 & 1, lane = (j2 >> 1) & 31, nt = (j2 >> 6) & 31, kt = j2 >> 11;
        int tig = lane & 3, g = lane >> 2;
        int k0 = kt*16 + tig*2 + 8*b, n = nt*8 + g;
        float v0 = w1[k0*256 + n], v1 = w1[(k0+1)*256 + n];
        g_w1f[j] = half ? pack_lo(v0, v1) : pack_hi(v0, v1);
    } else if (i < 86016) {
        int j = i - 69632;               // w2 frags, 16384 u32
        int half = j >> 13, j2 = j & 8191;
        int b = j2 & 1, lane = (j2 >> 1) & 31, nt = (j2 >> 6) & 7, kt = j2 >> 9;
        int tig = lane & 3, g = lane >> 2;
        int k0 = kt*16 + tig*2 + 8*b, n = nt*8 + g;
        float v0 = w2[k0*64 + n], v1 = w2[(k0+1)*64 + n];
        g_w2f[j] = half ? pack_lo(v0, v1) : pack_hi(v0, v1);
    }
}

// ---------------------------------------------------------------------------
// qkv via mma: 4 warps/block, warp = one 16-row m-tile; grid 256.
// x loaded directly from gmem and hi/lo-split inline (xfrag fused away).
// acc[24][4]: n-tiles 0-7 = q, 8-15 = k, 16-23 = v.
// ---------------------------------------------------------------------------
__global__ __launch_bounds__(128) void qkv_mma_kernel(const float* __restrict__ x)
{
    int wid = threadIdx.x >> 5, lane = threadIdx.x & 31;
    int mt = blockIdx.x*4 + wid;              // 0..1023
    int g = lane >> 2, tig = lane & 3;

    float acc[24][4];
#pragma unroll
    for (int nt = 0; nt < 24; nt++)
#pragma unroll
        for (int r = 0; r < 4; r++) acc[nt][r] = 0.f;

    int rowA = mt*16 + g, rowB = rowA + 8;
    const float* xA = x + (size_t)rowA*EMB_;
    const float* xB = x + (size_t)rowB*EMB_;

#pragma unroll 2
    for (int kt = 0; kt < 16; kt++) {
        int k0 = kt*16 + tig*2;
        float2 a0 = *(const float2*)&xA[k0];       // (row g,   k lo)
        float2 a1 = *(const float2*)&xB[k0];       // (row g+8, k lo)
        float2 a2 = *(const float2*)&xA[k0 + 8];   // (row g,   k hi)
        float2 a3 = *(const float2*)&xB[k0 + 8];   // (row g+8, k hi)
        u32 ah[4] = {pack_hi(a0.x, a0.y), pack_hi(a1.x, a1.y),
                     pack_hi(a2.x, a2.y), pack_hi(a3.x, a3.y)};
        u32 al[4] = {pack_lo(a0.x, a0.y), pack_lo(a1.x, a1.y),
                     pack_lo(a2.x, a2.y), pack_lo(a3.x, a3.y)};
#pragma unroll
        for (int nt = 0; nt < 24; nt++) {
            int idx = ((kt*24 + nt)*32 + lane)*2;
            uint2 bh = *(const uint2*)&g_wqf[idx];
            uint2 bl = *(const uint2*)&g_wqf[24576 + idx];
            mma_bf16(acc[nt], ah, bh.x, bh.y);
            mma_bf16(acc[nt], ah, bl.x, bl.y);
            mma_bf16(acc[nt], al, bh.x, bh.y);
        }
    }

    int row0 = mt*16 + g;
#pragma unroll
    for (int nt = 0; nt < 8; nt++) {
        int c = nt*8 + tig*2;
        float2 qa = make_float2(acc[nt][0] - acc[nt+8][0], acc[nt][1] - acc[nt+8][1]);
        float2 qb = make_float2(acc[nt][2] - acc[nt+8][2], acc[nt][3] - acc[nt+8][3]);
        *(float2*)&g_qmk[row0*64 + c]     = qa;
        *(float2*)&g_qmk[(row0+8)*64 + c] = qb;
        *(float2*)&g_v[row0*64 + c]     = make_float2(acc[nt+16][0], acc[nt+16][1]);
        *(float2*)&g_v[(row0+8)*64 + c] = make_float2(acc[nt+16][2], acc[nt+16][3]);
    }
}

// ---------------------------------------------------------------------------
// kNN v5: 512 blocks x 256 threads; 32 queries/block, 8 shards/query of 256.
// Pass1 (index-free min/max bubble) is shard-count invariant in total ops,
// so 8 shards buys pure parallelism. thr + eq-count rescan, sort, 8-way merge.
// smem: sx/sy/sz 3x2048 | sd 4096 | si 4096 = 56 KB
// ---------------------------------------------------------------------------
__global__ __launch_bounds__(256) void knn_kernel(const float* __restrict__ pos)
{
    extern __shared__ float ksm[];
    float* sx = ksm;                  // 2048
    float* sy = ksm + 2048;           // 2048
    float* sz = ksm + 4096;           // 2048
    float* sd = ksm + 6144;           // 4096
    int*   si = (int*)(ksm + 10240);  // 4096

    int batch = blockIdx.x >> 6;      // 8 batches
    int chunk = blockIdx.x & 63;      // 64 chunks of 32 queries
    const float* pb = pos + batch*N_*3;
    for (int e = threadIdx.x; e < N_*3; e += 256) {
        float v = pb[e];
        int j = e / 3, c = e - j*3;
        (c == 0 ? sx : c == 1 ? sy : sz)[j] = v;
    }
    __syncthreads();

    int q = threadIdx.x >> 3;          // 0..31 local query
    int s = threadIdx.x & 7;           // shard 0..7
    int qi = chunk*32 + q;
    float px = sx[qi], py = sy[qi], pz = sz[qi];

    const float2* sx2 = (const float2*)sx;
    const float2* sy2 = (const float2*)sy;
    const float2* sz2 = (const float2*)sz;
    int jj0 = s * 128;                 // 128 float2 pairs = 256 candidates

    // ---- Pass 1: distances-only top-16 via min/max bubble ----
    float bd[KNN_];
#pragma unroll
    for (int t = 0; t < KNN_; t++) bd[t] = 3.4e38f;

    for (int jj = jj0; jj < jj0 + 128; jj++) {
        float2 X = sx2[jj], Y = sy2[jj], Z = sz2[jj];
        float dxa = X.x - px, dya = Y.x - py, dza = Z.x - pz;
        float dxb = X.y - px, dyb = Y.y - py, dzb = Z.y - pz;
        float da = fmaf(dxa, dxa, fmaf(dya, dya, dza*dza));
        float db = fmaf(dxb, dxb, fmaf(dyb, dyb, dzb*dzb));
        float c = da;
#pragma unroll
        for (int t = 0; t < KNN_; t++) {
            float lo = fminf(bd[t], c);
            c = fmaxf(bd[t], c);
            bd[t] = lo;
        }
        c = db;
#pragma unroll
        for (int t = 0; t < KNN_; t++) {
            float lo = fminf(bd[t], c);
            c = fmaxf(bd[t], c);
            bd[t] = lo;
        }
    }

    // ---- threshold + equal-count ----
    float thr = bd[KNN_-1];
    int e_eq = 0;
#pragma unroll
    for (int t = 0; t < KNN_; t++) e_eq += (bd[t] == thr) ? 1 : 0;

    // ---- Pass 2: rescan, emit exactly 16 (d, idx) into smem ----
    int lb = (q*8 + s)*16;
    int cnt = 0, eq_taken = 0;
    for (int jj = jj0; jj < jj0 + 128; jj++) {
        float2 X = sx2[jj], Y = sy2[jj], Z = sz2[jj];
        float dxa = X.x - px, dya = Y.x - py, dza = Z.x - pz;
        float dxb = X.y - px, dyb = Y.y - py, dzb = Z.y - pz;
        float da = fmaf(dxa, dxa, fmaf(dya, dya, dza*dza));
        float db = fmaf(dxb, dxb, fmaf(dyb, dyb, dzb*dzb));
        if (da <= thr) {
            bool take = (da < thr) || (eq_taken < e_eq);
            if (take) {
                if (!(da < thr)) eq_taken++;
                sd[lb + cnt] = da;
                si[lb + cnt] = 2*jj;
                cnt++;
            }
        }
        if (db <= thr) {
            bool take = (db < thr) || (eq_taken < e_eq);
            if (take) {
                if (!(db < thr)) eq_taken++;
                sd[lb + cnt] = db;
                si[lb + cnt] = 2*jj + 1;
                cnt++;
            }
        }
    }

    // ---- per-thread sort of its 16 (d, i) ----
    {
        float od[KNN_]; int oi[KNN_];
#pragma unroll
        for (int t = 0; t < KNN_; t++) { od[t] = 3.4e38f; oi[t] = 0; }
#pragma unroll
        for (int u = 0; u < KNN_; u++) {
            float cd = sd[lb + u]; int ci = si[lb + u];
#pragma unroll
            for (int t = 0; t < KNN_; t++) {
                if (cd < od[t]) {
                    float td = od[t]; od[t] = cd; cd = td;
                    int   ti = oi[t]; oi[t] = ci; ci = ti;
                }
            }
        }
#pragma unroll
        for (int t = 0; t < KNN_; t++) { sd[lb+t] = od[t]; si[lb+t] = oi[t]; }
    }
    __syncthreads();

    // ---- 8-way merge (threads 0..31) ----
    if (threadIdx.x < 32) {
        int qq = threadIdx.x;
        int p[8] = {0,0,0,0,0,0,0,0};
        int base = qq*128;
        int obase = (batch*N_ + chunk*32 + qq)*KNN_;
#pragma unroll
        for (int t = 0; t < KNN_; t++) {
            float best = sd[base + p[0]]; int bsel = 0;
#pragma unroll
            for (int ss = 1; ss < 8; ss++) {
                float c = sd[base + ss*16 + p[ss]];
                if (c < best) { best = c; bsel = ss; }
            }
            g_idx[obase + t] = batch*N_ + si[base + bsel*16 + p[bsel]];
            p[bsel]++;
        }
    }
}

// ---------------------------------------------------------------------------
// Fused mma.sync kernel: 12 points/block, 12 warps (warp = point m-tile).
// ---------------------------------------------------------------------------
#define PPB 12
#define SMEM_FUSED_BYTES 156928

__global__ __launch_bounds__(384) void fused_kernel(
    const float* __restrict__ pos,
    const float* __restrict__ w_pos1, const float* __restrict__ b_pos1,
    const float* __restrict__ b_pos2,
    const float* __restrict__ b_att1, const float* __restrict__ b_att2,
    const float* __restrict__ w_out,  const float* __restrict__ b_out,
    float* __restrict__ out)
{
    extern __shared__ u32 smu[];
    u32* sW1F = smu;                 // 16384
    u32* sW2F = smu + 16384;         // 16384
    u32* sWPF = smu + 32768;         // 4096
    float* sF   = (float*)(smu + 36864);
    float* sRel = sF;                // 768 (192 x 4)
    float* sWP1 = sF + 768;          // 192
    float* sBp1 = sF + 960;          // 64
    float* sBp2 = sF + 1024;         // 64
    float* sBa1 = sF + 1088;         // 256
    float* sBa2 = sF + 1344;         // 64
    float* sAgg = sF + 1408;         // 768
    int*   sNbr = (int*)(sF + 2176); // 192

    const int tid  = threadIdx.x;
    const int wid  = tid >> 5;
    const int lane = tid & 31;
    const int gp0  = blockIdx.x * PPB;

    // ---- staging ----
    {
        const uint4* s1 = (const uint4*)g_w1f;  uint4* d1 = (uint4*)sW1F;
        const uint4* s2 = (const uint4*)g_w2f;  uint4* d2 = (uint4*)sW2F;
        for (int i = tid; i < 4096; i += 384) { d1[i] = s1[i]; d2[i] = s2[i]; }
        const uint4* s3 = (const uint4*)g_wpf;  uint4* d3 = (uint4*)sWPF;
        for (int i = tid; i < 1024; i += 384) d3[i] = s3[i];
    }
    if (tid < 192) sWP1[tid] = w_pos1[tid];
    if (tid < 64) {
        sBp1[tid] = b_pos1[tid];
        sBp2[tid] = b_pos2[tid];
        sBa2[tid] = b_att2[tid];
    }
    if (tid < 256) sBa1[tid] = b_att1[tid];
    if (tid < 16*PPB) {
        int gp = gp0 + (tid >> 4);
        if (gp >= NPTS_) gp = NPTS_ - 1;           // clamp (tail block)
        int nbr = g_idx[gp*KNN_ + (tid & 15)];
        sNbr[tid] = nbr;
        sRel[tid*4+0] = pos[nbr*3+0] - pos[gp*3+0];
        sRel[tid*4+1] = pos[nbr*3+1] - pos[gp*3+1];
        sRel[tid*4+2] = pos[nbr*3+2] - pos[gp*3+2];
    }
    __syncthreads();

    const int mt  = wid;            // point / m-tile (0..11)
    const int g   = lane >> 2;
    const int tig = lane & 3;
    const int prA = mt*16 + g;      // pair-row A
    const int prB = prA + 8;        // pair-row B

    // ---- P1: mid = relu(rel @ wp1 + bp1) -> A-frags (regs) ----
    u32 midH[16], midL[16];
    {
        float rA0 = sRel[prA*4+0], rA1 = sRel[prA*4+1], rA2 = sRel[prA*4+2];
        float rB0 = sRel[prB*4+0], rB1 = sRel[prB*4+1], rB2 = sRel[prB*4+2];
#pragma unroll
        for (int kt = 0; kt < 4; kt++)
#pragma unroll
            for (int cb = 0; cb < 2; cb++) {
                int c0 = kt*16 + cb*8 + tig*2;
                float wx0 = sWP1[c0],   wy0 = sWP1[64+c0],   wz0 = sWP1[128+c0];
                float wx1 = sWP1[c0+1], wy1 = sWP1[64+c0+1], wz1 = sWP1[128+c0+1];
                float bb0 = sBp1[c0], bb1 = sBp1[c0+1];
                float a0 = fmaxf(rA0*wx0 + rA1*wy0 + rA2*wz0 + bb0, 0.f);
                float a1 = fmaxf(rA0*wx1 + rA1*wy1 + rA2*wz1 + bb1, 0.f);
                float b0 = fmaxf(rB0*wx0 + rB1*wy0 + rB2*wz0 + bb0, 0.f);
                float b1 = fmaxf(rB0*wx1 + rB1*wy1 + rB2*wz1 + bb1, 0.f);
                int r = kt*4 + cb*2;
                midH[r]   = pack_hi(a0, a1);  midL[r]   = pack_lo(a0, a1);
                midH[r+1] = pack_hi(b0, b1);  midL[r+1] = pack_lo(b0, b1);
            }
    }

    // ---- P2: rpe = mid @ wp2 (mma, split x3) ----
    float rpe[8][4];
#pragma unroll
    for (int nt = 0; nt < 8; nt++)
#pragma unroll
        for (int r = 0; r < 4; r++) rpe[nt][r] = 0.f;
#pragma unroll
    for (int kt = 0; kt < 4; kt++) {
#pragma unroll
        for (int nt = 0; nt < 8; nt++) {
            int idx = ((kt*8 + nt)*32 + lane)*2;
            uint2 bh = *(const uint2*)&sWPF[idx];
            uint2 bl = *(const uint2*)&sWPF[2048 + idx];
            mma_bf16(rpe[nt], &midH[kt*4], bh.x, bh.y);
            mma_bf16(rpe[nt], &midH[kt*4], bl.x, bl.y);
            mma_bf16(rpe[nt], &midL[kt*4], bh.x, bh.y);
        }
    }

    // ---- P2 epilogue: h frags (regs) + vn (regs) ----
    u32 hH[16], hL[16];
    float vnr[8][4];
    {
        int nA = sNbr[prA], nB = sNbr[prB];
#pragma unroll
        for (int nt = 0; nt < 8; nt++) {
            int c0 = nt*8 + tig*2;
            float b0 = sBp2[c0], b1 = sBp2[c0+1];
            float2 qA = *(const float2*)&g_qmk[nA*64 + c0];
            float2 qB = *(const float2*)&g_qmk[nB*64 + c0];
            float2 vA = *(const float2*)&g_v[nA*64 + c0];
            float2 vB = *(const float2*)&g_v[nB*64 + c0];
            float r0 = rpe[nt][0] + b0, r1 = rpe[nt][1] + b1;
            float r2 = rpe[nt][2] + b0, r3 = rpe[nt][3] + b1;
            vnr[nt][0] = vA.x + r0;  vnr[nt][1] = vA.y + r1;
            vnr[nt][2] = vB.x + r2;  vnr[nt][3] = vB.y + r3;
            int fr = (nt >> 1)*4 + (nt & 1)*2;
            float hA0 = qA.x + r0, hA1 = qA.y + r1;
            float hB0 = qB.x + r2, hB1 = qB.y + r3;
            hH[fr]   = pack_hi(hA0, hA1);  hL[fr]   = pack_lo(hA0, hA1);
            hH[fr+1] = pack_hi(hB0, hB1);  hL[fr+1] = pack_lo(hB0, hB1);
        }
    }

    // ---- MMA1 + epilogue + MMA2, chunked over t columns ----
    float sim[8][4];
#pragma unroll
    for (int nt = 0; nt < 8; nt++)
#pragma unroll
        for (int r = 0; r < 4; r++) sim[nt][r] = 0.f;

#pragma unroll
    for (int ch = 0; ch < 4; ch++) {
        float tacc[8][4];
#pragma unroll
        for (int nt = 0; nt < 8; nt++)
#pragma unroll
            for (int r = 0; r < 4; r++) tacc[nt][r] = 0.f;
#pragma unroll
        for (int kt = 0; kt < 4; kt++) {
#pragma unroll
            for (int nt = 0; nt < 8; nt++) {
                int idx = ((kt*32 + ch*8 + nt)*32 + lane)*2;
                uint2 bh = *(const uint2*)&sW1F[idx];
                uint2 bl = *(const uint2*)&sW1F[8192 + idx];
                mma_bf16(tacc[nt], &hH[kt*4], bh.x, bh.y);
                mma_bf16(tacc[nt], &hH[kt*4], bl.x, bl.y);
                mma_bf16(tacc[nt], &hL[kt*4], bh.x, bh.y);
            }
        }
        // epilogue: t = relu(tacc + ba1) -> A2 frags
        u32 tH[16], tL[16];
#pragma unroll
        for (int nt = 0; nt < 8; nt++) {
            int c0 = ch*64 + nt*8 + tig*2;
            float b0 = sBa1[c0], b1 = sBa1[c0+1];
            float t0 = fmaxf(tacc[nt][0] + b0, 0.f);
            float t1 = fmaxf(tacc[nt][1] + b1, 0.f);
            float t2 = fmaxf(tacc[nt][2] + b0, 0.f);
            float t3 = fmaxf(tacc[nt][3] + b1, 0.f);
            int fr = (nt >> 1)*4 + (nt & 1)*2;
            tH[fr]   = pack_hi(t0, t1);  tL[fr]   = pack_lo(t0, t1);
            tH[fr+1] = pack_hi(t2, t3);  tL[fr+1] = pack_lo(t2, t3);
        }
        // MMA2 partial over this chunk's K
#pragma unroll
        for (int kl = 0; kl < 4; kl++) {
            int kt2 = ch*4 + kl;
#pragma unroll
            for (int nt = 0; nt < 8; nt++) {
                int idx = ((kt2*8 + nt)*32 + lane)*2;
                uint2 bh = *(const uint2*)&sW2F[idx];
                uint2 bl = *(const uint2*)&sW2F[8192 + idx];
                mma_bf16(sim[nt], &tH[kl*4], bh.x, bh.y);
                mma_bf16(sim[nt], &tH[kl*4], bl.x, bl.y);
                mma_bf16(sim[nt], &tL[kl*4], bh.x, bh.y);
            }
        }
    }

    // ---- sim bias + softmax (rows A and B) ----
#pragma unroll
    for (int nt = 0; nt < 8; nt++) {
        int c0 = nt*8 + tig*2;
        float b0 = sBa2[c0], b1 = sBa2[c0+1];
        sim[nt][0] += b0; sim[nt][1] += b1;
        sim[nt][2] += b0; sim[nt][3] += b1;
    }
    {
        float mxA = -3.4e38f, mxB = -3.4e38f;
#pragma unroll
        for (int nt = 0; nt < 8; nt++) {
            mxA = fmaxf(mxA, fmaxf(sim[nt][0], sim[nt][1]));
            mxB = fmaxf(mxB, fmaxf(sim[nt][2], sim[nt][3]));
        }
        mxA = fmaxf(mxA, __shfl_xor_sync(0xffffffffu, mxA, 1));
        mxA = fmaxf(mxA, __shfl_xor_sync(0xffffffffu, mxA, 2));
        mxB = fmaxf(mxB, __shfl_xor_sync(0xffffffffu, mxB, 1));
        mxB = fmaxf(mxB, __shfl_xor_sync(0xffffffffu, mxB, 2));
        float sA = 0.f, sB = 0.f;
#pragma unroll
        for (int nt = 0; nt < 8; nt++) {
            sim[nt][0] = __expf(sim[nt][0] - mxA); sA += sim[nt][0];
            sim[nt][1] = __expf(sim[nt][1] - mxA); sA += sim[nt][1];
            sim[nt][2] = __expf(sim[nt][2] - mxB); sB += sim[nt][2];
            sim[nt][3] = __expf(sim[nt][3] - mxB); sB += sim[nt][3];
        }
        sA += __shfl_xor_sync(0xffffffffu, sA, 1);
        sA += __shfl_xor_sync(0xffffffffu, sA, 2);
        sB += __shfl_xor_sync(0xffffffffu, sB, 1);
        sB += __shfl_xor_sync(0xffffffffu, sB, 2);
        float iA = 1.f / sA, iB = 1.f / sB;
#pragma unroll
        for (int nt = 0; nt < 8; nt++) {
            sim[nt][0] *= iA; sim[nt][1] *= iA;
            sim[nt][2] *= iB; sim[nt][3] *= iB;
        }
    }

    // ---- channel norm over 16 neighbors + aggregate ----
#pragma unroll
    for (int nt = 0; nt < 8; nt++) {
#pragma unroll
        for (int p = 0; p < 2; p++) {
            float a0 = sim[nt][p], a1 = sim[nt][2+p];
            float s2 = a0*a0 + a1*a1;
            float dv = a0*vnr[nt][p] + a1*vnr[nt][2+p];
            s2 += __shfl_xor_sync(0xffffffffu, s2, 4);
            s2 += __shfl_xor_sync(0xffffffffu, s2, 8);
            s2 += __shfl_xor_sync(0xffffffffu, s2, 16);
            dv += __shfl_xor_sync(0xffffffffu, dv, 4);
            dv += __shfl_xor_sync(0xffffffffu, dv, 8);
            dv += __shfl_xor_sync(0xffffffffu, dv, 16);
            if (g == 0)
                sAgg[mt*64 + nt*8 + tig*2 + p] = dv / fmaxf(sqrtf(s2), 1e-12f);
        }
    }
    __syncthreads();

    // ---- P7: out = agg @ w_out + b_out ----
    if (tid < 256) {
        float acc[PPB];
        float bb = b_out[tid];
#pragma unroll
        for (int p = 0; p < PPB; p++) acc[p] = bb;
        for (int k = 0; k < 64; k++) {
            float w = w_out[k*256 + tid];
#pragma unroll
            for (int p = 0; p < PPB; p++)
                acc[p] += sAgg[p*64 + k] * w;
        }
#pragma unroll
        for (int p = 0; p < PPB; p++)
            if (gp0 + p < NPTS_)
                out[(gp0 + p)*256 + tid] = acc[p];
    }
}

// ---------------------------------------------------------------------------
extern "C" void kernel_launch(void* const* d_in, const int* in_sizes, int n_in,
                              void* d_out, int out_size)
{
    const float* x      = (const float*)d_in[0];
    const float* pos    = (const float*)d_in[1];
    const float* w_qkv  = (const float*)d_in[2];
    const float* w_pos1 = (const float*)d_in[3];
    const float* b_pos1 = (const float*)d_in[4];
    const float* w_pos2 = (const float*)d_in[5];
    const float* b_pos2 = (const float*)d_in[6];
    const float* w_att1 = (const float*)d_in[7];
    const float* b_att1 = (const float*)d_in[8];
    const float* w_att2 = (const float*)d_in[9];
    const float* b_att2 = (const float*)d_in[10];
    const float* w_out  = (const float*)d_in[11];
    const float* b_out  = (const float*)d_in[12];
    float* out = (float*)d_out;

    (void)in_sizes; (void)n_in; (void)out_size;

    cudaFuncSetAttribute(fused_kernel,
                         cudaFuncAttributeMaxDynamicSharedMemorySize, SMEM_FUSED_BYTES);
    const int smem_knn = (6144 + 4096 + 4096) * 4;
    cudaFuncSetAttribute(knn_kernel,
                         cudaFuncAttributeMaxDynamicSharedMemorySize, smem_knn);

    prep_kernel<<<336, 256>>>(w_qkv, w_att1, w_att2, w_pos2);
    qkv_mma_kernel<<<256, 128>>>(x);
    knn_kernel<<<512, 256, smem_knn>>>(pos);
    fused_kernel<<<(NPTS_ + PPB - 1)/PPB, 384, SMEM_FUSED_BYTES>>>(
        pos, w_pos1, b_pos1, b_pos2, b_att1, b_att2, w_out, b_out, out);
}

// round 15
// speedup vs baseline: 1.2081x; 1.2081x over previous
#include <cuda_runtime.h>
#include <cuda_bf16.h>

#define B_    8
#define N_    2048
#define EMB_  256
#define KNN_  16
#define NPTS_ (B_*N_)

typedef unsigned long long ull;
typedef unsigned int u32;

// bf16 hi/lo split packers (lower col -> low 16 bits)
__device__ __forceinline__ u32 pack_hi(float v0, float v1) {
    __nv_bfloat162 h = __floats2bfloat162_rn(v0, v1);
    return *(u32*)&h;
}
__device__ __forceinline__ u32 pack_lo(float v0, float v1) {
    __nv_bfloat16 h0 = __float2bfloat16(v0), h1 = __float2bfloat16(v1);
    __nv_bfloat162 l = __floats2bfloat162_rn(v0 - __bfloat162float(h0),
                                             v1 - __bfloat162float(h1));
    return *(u32*)&l;
}

// m16n8k16 bf16 mma, f32 accum.  NOT volatile: pure register dataflow, so the
// scheduler may interleave independent mma chains (critical for HMMA pipelining).
__device__ __forceinline__ void mma_bf16(float d[4], const u32 a[4], u32 b0, u32 b1) {
    asm("mma.sync.aligned.m16n8k16.row.col.f32.bf16.bf16.f32 "
        "{%0,%1,%2,%3}, {%4,%5,%6,%7}, {%8,%9}, {%0,%1,%2,%3};"
        : "+f"(d[0]), "+f"(d[1]), "+f"(d[2]), "+f"(d[3])
        : "r"(a[0]), "r"(a[1]), "r"(a[2]), "r"(a[3]), "r"(b0), "r"(b1));
}

// ---- Scratch (device globals) ----
__device__ float g_qmk[NPTS_*64];
__device__ float g_v  [NPTS_*64];
__device__ int   g_idx[NPTS_*KNN_];
// B-fragment-ordered weights, bf16 hi half then lo half:
__device__ __align__(16) u32 g_wqf[49152];        // w_qkv  [kt16][nt24][lane][b2] x2
__device__ __align__(16) u32 g_w1f[16384];        // w_att1 [kt4][nt32][lane][b2] x2
__device__ __align__(16) u32 g_w2f[16384];        // w_att2 [kt16][nt8][lane][b2] x2
__device__ __align__(16) u32 g_wpf[4096];         // w_pos2 [kt4][nt8][lane][b2] x2
// x as A-fragments (hi/lo): [mtile1024][kt16][lane32][r4]
__device__ __align__(16) u32 g_xfh[2097152];
__device__ __align__(16) u32 g_xfl[2097152];

// ---------------------------------------------------------------------------
__global__ __launch_bounds__(256) void prep_kernel(
    const float* __restrict__ wq, const float* __restrict__ w1,
    const float* __restrict__ w2, const float* __restrict__ wp)
{
    int i = blockIdx.x*256 + threadIdx.x;
    if (i < 49152) {
        int half = (i >= 24576);
        int j2 = half ? i - 24576 : i;
        int b = j2 & 1, lane = (j2 >> 1) & 31;
        int ktnt = j2 >> 6;            // 0..383
        int nt = ktnt % 24, kt = ktnt / 24;
        int tig = lane & 3, g = lane >> 2;
        int k0 = kt*16 + tig*2 + 8*b, n = nt*8 + g;
        float v0 = wq[k0*192 + n], v1 = wq[(k0+1)*192 + n];
        g_wqf[i] = half ? pack_lo(v0, v1) : pack_hi(v0, v1);
    } else if (i < 53248) {
        int j = i - 49152;               // wp2 frags, 4096 u32
        int half = j >> 11, j2 = j & 2047;
        int b = j2 & 1, lane = (j2 >> 1) & 31, nt = (j2 >> 6) & 7, kt = j2 >> 9;
        int tig = lane & 3, g = lane >> 2;
        int k0 = kt*16 + tig*2 + 8*b, n = nt*8 + g;
        float v0 = wp[k0*64 + n], v1 = wp[(k0+1)*64 + n];
        g_wpf[j] = half ? pack_lo(v0, v1) : pack_hi(v0, v1);
    } else if (i < 69632) {
        int j = i - 53248;               // w1 frags, 16384 u32
        int half = j >> 13, j2 = j & 8191;
        int b = j2 & 1, lane = (j2 >> 1) & 31, nt = (j2 >> 6) & 31, kt = j2 >> 11;
        int tig = lane & 3, g = lane >> 2;
        int k0 = kt*16 + tig*2 + 8*b, n = nt*8 + g;
        float v0 = w1[k0*256 + n], v1 = w1[(k0+1)*256 + n];
        g_w1f[j] = half ? pack_lo(v0, v1) : pack_hi(v0, v1);
    } else if (i < 86016) {
        int j = i - 69632;               // w2 frags, 16384 u32
        int half = j >> 13, j2 = j & 8191;
        int b = j2 & 1, lane = (j2 >> 1) & 31, nt = (j2 >> 6) & 7, kt = j2 >> 9;
        int tig = lane & 3, g = lane >> 2;
        int k0 = kt*16 + tig*2 + 8*b, n = nt*8 + g;
        float v0 = w2[k0*64 + n], v1 = w2[(k0+1)*64 + n];
        g_w2f[j] = half ? pack_lo(v0, v1) : pack_hi(v0, v1);
    }
}

// ---------------------------------------------------------------------------
// xfrag: convert x -> bf16 hi/lo A-fragments (coalesced; R13-proven).
// ---------------------------------------------------------------------------
__global__ __launch_bounds__(256) void xfrag_kernel(const float* __restrict__ x)
{
    int j = blockIdx.x*256 + threadIdx.x;     // < 2097152
    int r = j & 3;
    int lane = (j >> 2) & 31;
    int kt = (j >> 7) & 15;
    int m  = j >> 11;
    int g = lane >> 2, tig = lane & 3;
    int row = m*16 + (r & 1)*8 + g;
    int k   = kt*16 + (r >> 1)*8 + tig*2;
    float2 xv = *(const float2*)&x[row*256 + k];
    g_xfh[j] = pack_hi(xv.x, xv.y);
    g_xfl[j] = pack_lo(xv.x, xv.y);
}

// ---------------------------------------------------------------------------
// qkv via mma: 4 warps/block, warp = one 16-row m-tile; grid 256.
// ---------------------------------------------------------------------------
__global__ __launch_bounds__(128) void qkv_mma_kernel()
{
    int wid = threadIdx.x >> 5, lane = threadIdx.x & 31;
    int mt = blockIdx.x*4 + wid;              // 0..1023
    int g = lane >> 2, tig = lane & 3;

    float acc[24][4];
#pragma unroll
    for (int nt = 0; nt < 24; nt++)
#pragma unroll
        for (int r = 0; r < 4; r++) acc[nt][r] = 0.f;

#pragma unroll 4
    for (int kt = 0; kt < 16; kt++) {
        int abase = ((mt*16 + kt)*32 + lane)*4;
        uint4 ah4 = *(const uint4*)&g_xfh[abase];
        uint4 al4 = *(const uint4*)&g_xfl[abase];
        u32 ah[4] = {ah4.x, ah4.y, ah4.z, ah4.w};
        u32 al[4] = {al4.x, al4.y, al4.z, al4.w};
#pragma unroll
        for (int nt = 0; nt < 24; nt++) {
            int idx = ((kt*24 + nt)*32 + lane)*2;
            uint2 bh = *(const uint2*)&g_wqf[idx];
            uint2 bl = *(const uint2*)&g_wqf[24576 + idx];
            mma_bf16(acc[nt], ah, bh.x, bh.y);
            mma_bf16(acc[nt], ah, bl.x, bl.y);
            mma_bf16(acc[nt], al, bh.x, bh.y);
        }
    }

    int row0 = mt*16 + g;
#pragma unroll
    for (int nt = 0; nt < 8; nt++) {
        int c = nt*8 + tig*2;
        float2 qa = make_float2(acc[nt][0] - acc[nt+8][0], acc[nt][1] - acc[nt+8][1]);
        float2 qb = make_float2(acc[nt][2] - acc[nt+8][2], acc[nt][3] - acc[nt+8][3]);
        *(float2*)&g_qmk[row0*64 + c]     = qa;
        *(float2*)&g_qmk[(row0+8)*64 + c] = qb;
        *(float2*)&g_v[row0*64 + c]     = make_float2(acc[nt+16][0], acc[nt+16][1]);
        *(float2*)&g_v[(row0+8)*64 + c] = make_float2(acc[nt+16][2], acc[nt+16][3]);
    }
}

// ---------------------------------------------------------------------------
// kNN v4 (R13 winner): 256 blocks x 256 threads; 64 q/block, 4 shards x 512.
// Index-free min/max bubble, thr+eq rescan, per-thread sort, 4-way merge.
// ---------------------------------------------------------------------------
__global__ __launch_bounds__(256) void knn_kernel(const float* __restrict__ pos)
{
    extern __shared__ float ksm[];
    float* sx = ksm;                  // 2048
    float* sy = ksm + 2048;           // 2048
    float* sz = ksm + 4096;           // 2048
    float* sd = ksm + 6144;           // 4096
    int*   si = (int*)(ksm + 10240);  // 4096

    int batch = blockIdx.x >> 5;      // 8 batches
    int chunk = blockIdx.x & 31;      // 32 chunks of 64 queries
    const float* pb = pos + batch*N_*3;
    for (int e = threadIdx.x; e < N_*3; e += 256) {
        float v = pb[e];
        int j = e / 3, c = e - j*3;
        (c == 0 ? sx : c == 1 ? sy : sz)[j] = v;
    }
    __syncthreads();

    int q = threadIdx.x >> 2;          // 0..63 local query
    int s = threadIdx.x & 3;           // shard 0..3
    int qi = chunk*64 + q;
    float px = sx[qi], py = sy[qi], pz = sz[qi];

    const float2* sx2 = (const float2*)sx;
    const float2* sy2 = (const float2*)sy;
    const float2* sz2 = (const float2*)sz;
    int jj0 = s * 256;                 // 256 float2 pairs = 512 candidates

    // ---- Pass 1: distances-only top-16 via min/max bubble ----
    float bd[KNN_];
#pragma unroll
    for (int t = 0; t < KNN_; t++) bd[t] = 3.4e38f;

    for (int jj = jj0; jj < jj0 + 256; jj++) {
        float2 X = sx2[jj], Y = sy2[jj], Z = sz2[jj];
        float dxa = X.x - px, dya = Y.x - py, dza = Z.x - pz;
        float dxb = X.y - px, dyb = Y.y - py, dzb = Z.y - pz;
        float da = fmaf(dxa, dxa, fmaf(dya, dya, dza*dza));
        float db = fmaf(dxb, dxb, fmaf(dyb, dyb, dzb*dzb));
        float c = da;
#pragma unroll
        for (int t = 0; t < KNN_; t++) {
            float lo = fminf(bd[t], c);
            c = fmaxf(bd[t], c);
            bd[t] = lo;
        }
        c = db;
#pragma unroll
        for (int t = 0; t < KNN_; t++) {
            float lo = fminf(bd[t], c);
            c = fmaxf(bd[t], c);
            bd[t] = lo;
        }
    }

    // ---- threshold + equal-count ----
    float thr = bd[KNN_-1];
    int e_eq = 0;
#pragma unroll
    for (int t = 0; t < KNN_; t++) e_eq += (bd[t] == thr) ? 1 : 0;

    // ---- Pass 2: rescan, emit exactly 16 (d, idx) into smem ----
    int lb = (q*4 + s)*16;
    int cnt = 0, eq_taken = 0;
    for (int jj = jj0; jj < jj0 + 256; jj++) {
        float2 X = sx2[jj], Y = sy2[jj], Z = sz2[jj];
        float dxa = X.x - px, dya = Y.x - py, dza = Z.x - pz;
        float dxb = X.y - px, dyb = Y.y - py, dzb = Z.y - pz;
        float da = fmaf(dxa, dxa, fmaf(dya, dya, dza*dza));
        float db = fmaf(dxb, dxb, fmaf(dyb, dyb, dzb*dzb));
        if (da <= thr) {
            bool take = (da < thr) || (eq_taken < e_eq);
            if (take) {
                if (!(da < thr)) eq_taken++;
                sd[lb + cnt] = da;
                si[lb + cnt] = 2*jj;
                cnt++;
            }
        }
        if (db <= thr) {
            bool take = (db < thr) || (eq_taken < e_eq);
            if (take) {
                if (!(db < thr)) eq_taken++;
                sd[lb + cnt] = db;
                si[lb + cnt] = 2*jj + 1;
                cnt++;
            }
        }
    }

    // ---- per-thread sort of its 16 (d, i) ----
    {
        float od[KNN_]; int oi[KNN_];
#pragma unroll
        for (int t = 0; t < KNN_; t++) { od[t] = 3.4e38f; oi[t] = 0; }
#pragma unroll
        for (int u = 0; u < KNN_; u++) {
            float cd = sd[lb + u]; int ci = si[lb + u];
#pragma unroll
            for (int t = 0; t < KNN_; t++) {
                if (cd < od[t]) {
                    float td = od[t]; od[t] = cd; cd = td;
                    int   ti = oi[t]; oi[t] = ci; ci = ti;
                }
            }
        }
#pragma unroll
        for (int t = 0; t < KNN_; t++) { sd[lb+t] = od[t]; si[lb+t] = oi[t]; }
    }
    __syncthreads();

    // ---- 4-way merge (threads 0..63) ----
    if (threadIdx.x < 64) {
        int qq = threadIdx.x;
        int p[4] = {0,0,0,0};
        int base = qq*64;
        int obase = (batch*N_ + chunk*64 + qq)*KNN_;
#pragma unroll
        for (int t = 0; t < KNN_; t++) {
            float best = sd[base + p[0]]; int bsel = 0;
            float c1 = sd[base + 16 + p[1]];
            if (c1 < best) { best = c1; bsel = 1; }
            float c2 = sd[base + 32 + p[2]];
            if (c2 < best) { best = c2; bsel = 2; }
            float c3 = sd[base + 48 + p[3]];
            if (c3 < best) { best = c3; bsel = 3; }
            g_idx[obase + t] = batch*N_ + si[base + bsel*16 + p[bsel]];
            p[bsel]++;
        }
    }
}

// ---------------------------------------------------------------------------
// Fused mma.sync kernel: 12 points/block, 12 warps (warp = point m-tile).
// ---------------------------------------------------------------------------
#define PPB 12
#define SMEM_FUSED_BYTES 156928

__global__ __launch_bounds__(384) void fused_kernel(
    const float* __restrict__ pos,
    const float* __restrict__ w_pos1, const float* __restrict__ b_pos1,
    const float* __restrict__ b_pos2,
    const float* __restrict__ b_att1, const float* __restrict__ b_att2,
    const float* __restrict__ w_out,  const float* __restrict__ b_out,
    float* __restrict__ out)
{
    extern __shared__ u32 smu[];
    u32* sW1F = smu;                 // 16384
    u32* sW2F = smu + 16384;         // 16384
    u32* sWPF = smu + 32768;         // 4096
    float* sF   = (float*)(smu + 36864);
    float* sRel = sF;                // 768 (192 x 4)
    float* sWP1 = sF + 768;          // 192
    float* sBp1 = sF + 960;          // 64
    float* sBp2 = sF + 1024;         // 64
    float* sBa1 = sF + 1088;         // 256
    float* sBa2 = sF + 1344;         // 64
    float* sAgg = sF + 1408;         // 768
    int*   sNbr = (int*)(sF + 2176); // 192

    const int tid  = threadIdx.x;
    const int wid  = tid >> 5;
    const int lane = tid & 31;
    const int gp0  = blockIdx.x * PPB;

    // ---- staging ----
    {
        const uint4* s1 = (const uint4*)g_w1f;  uint4* d1 = (uint4*)sW1F;
        const uint4* s2 = (const uint4*)g_w2f;  uint4* d2 = (uint4*)sW2F;
        for (int i = tid; i < 4096; i += 384) { d1[i] = s1[i]; d2[i] = s2[i]; }
        const uint4* s3 = (const uint4*)g_wpf;  uint4* d3 = (uint4*)sWPF;
        for (int i = tid; i < 1024; i += 384) d3[i] = s3[i];
    }
    if (tid < 192) sWP1[tid] = w_pos1[tid];
    if (tid < 64) {
        sBp1[tid] = b_pos1[tid];
        sBp2[tid] = b_pos2[tid];
        sBa2[tid] = b_att2[tid];
    }
    if (tid < 256) sBa1[tid] = b_att1[tid];
    if (tid < 16*PPB) {
        int gp = gp0 + (tid >> 4);
        if (gp >= NPTS_) gp = NPTS_ - 1;           // clamp (tail block)
        int nbr = g_idx[gp*KNN_ + (tid & 15)];
        sNbr[tid] = nbr;
        sRel[tid*4+0] = pos[nbr*3+0] - pos[gp*3+0];
        sRel[tid*4+1] = pos[nbr*3+1] - pos[gp*3+1];
        sRel[tid*4+2] = pos[nbr*3+2] - pos[gp*3+2];
    }
    __syncthreads();

    const int mt  = wid;            // point / m-tile (0..11)
    const int g   = lane >> 2;
    const int tig = lane & 3;
    const int prA = mt*16 + g;      // pair-row A
    const int prB = prA + 8;        // pair-row B

    // ---- P1: mid = relu(rel @ wp1 + bp1) -> A-frags (regs) ----
    u32 midH[16], midL[16];
    {
        float rA0 = sRel[prA*4+0], rA1 = sRel[prA*4+1], rA2 = sRel[prA*4+2];
        float rB0 = sRel[prB*4+0], rB1 = sRel[prB*4+1], rB2 = sRel[prB*4+2];
#pragma unroll
        for (int kt = 0; kt < 4; kt++)
#pragma unroll
            for (int cb = 0; cb < 2; cb++) {
                int c0 = kt*16 + cb*8 + tig*2;
                float wx0 = sWP1[c0],   wy0 = sWP1[64+c0],   wz0 = sWP1[128+c0];
                float wx1 = sWP1[c0+1], wy1 = sWP1[64+c0+1], wz1 = sWP1[128+c0+1];
                float bb0 = sBp1[c0], bb1 = sBp1[c0+1];
                float a0 = fmaxf(rA0*wx0 + rA1*wy0 + rA2*wz0 + bb0, 0.f);
                float a1 = fmaxf(rA0*wx1 + rA1*wy1 + rA2*wz1 + bb1, 0.f);
                float b0 = fmaxf(rB0*wx0 + rB1*wy0 + rB2*wz0 + bb0, 0.f);
                float b1 = fmaxf(rB0*wx1 + rB1*wy1 + rB2*wz1 + bb1, 0.f);
                int r = kt*4 + cb*2;
                midH[r]   = pack_hi(a0, a1);  midL[r]   = pack_lo(a0, a1);
                midH[r+1] = pack_hi(b0, b1);  midL[r+1] = pack_lo(b0, b1);
            }
    }

    // ---- P2: rpe = mid @ wp2 (mma, split x3) ----
    float rpe[8][4];
#pragma unroll
    for (int nt = 0; nt < 8; nt++)
#pragma unroll
        for (int r = 0; r < 4; r++) rpe[nt][r] = 0.f;
#pragma unroll
    for (int kt = 0; kt < 4; kt++) {
#pragma unroll
        for (int nt = 0; nt < 8; nt++) {
            int idx = ((kt*8 + nt)*32 + lane)*2;
            uint2 bh = *(const uint2*)&sWPF[idx];
            uint2 bl = *(const uint2*)&sWPF[2048 + idx];
            mma_bf16(rpe[nt], &midH[kt*4], bh.x, bh.y);
            mma_bf16(rpe[nt], &midH[kt*4], bl.x, bl.y);
            mma_bf16(rpe[nt], &midL[kt*4], bh.x, bh.y);
        }
    }

    // ---- P2 epilogue: h frags (regs) + vn (regs) ----
    u32 hH[16], hL[16];
    float vnr[8][4];
    {
        int nA = sNbr[prA], nB = sNbr[prB];
#pragma unroll
        for (int nt = 0; nt < 8; nt++) {
            int c0 = nt*8 + tig*2;
            float b0 = sBp2[c0], b1 = sBp2[c0+1];
            float2 qA = *(const float2*)&g_qmk[nA*64 + c0];
            float2 qB = *(const float2*)&g_qmk[nB*64 + c0];
            float2 vA = *(const float2*)&g_v[nA*64 + c0];
            float2 vB = *(const float2*)&g_v[nB*64 + c0];
            float r0 = rpe[nt][0] + b0, r1 = rpe[nt][1] + b1;
            float r2 = rpe[nt][2] + b0, r3 = rpe[nt][3] + b1;
            vnr[nt][0] = vA.x + r0;  vnr[nt][1] = vA.y + r1;
            vnr[nt][2] = vB.x + r2;  vnr[nt][3] = vB.y + r3;
            int fr = (nt >> 1)*4 + (nt & 1)*2;
            float hA0 = qA.x + r0, hA1 = qA.y + r1;
            float hB0 = qB.x + r2, hB1 = qB.y + r3;
            hH[fr]   = pack_hi(hA0, hA1);  hL[fr]   = pack_lo(hA0, hA1);
            hH[fr+1] = pack_hi(hB0, hB1);  hL[fr+1] = pack_lo(hB0, hB1);
        }
    }

    // ---- MMA1 + epilogue + MMA2, chunked over t columns ----
    float sim[8][4];
#pragma unroll
    for (int nt = 0; nt < 8; nt++)
#pragma unroll
        for (int r = 0; r < 4; r++) sim[nt][r] = 0.f;

#pragma unroll
    for (int ch = 0; ch < 4; ch++) {
        float tacc[8][4];
#pragma unroll
        for (int nt = 0; nt < 8; nt++)
#pragma unroll
            for (int r = 0; r < 4; r++) tacc[nt][r] = 0.f;
#pragma unroll
        for (int kt = 0; kt < 4; kt++) {
#pragma unroll
            for (int nt = 0; nt < 8; nt++) {
                int idx = ((kt*32 + ch*8 + nt)*32 + lane)*2;
                uint2 bh = *(const uint2*)&sW1F[idx];
                uint2 bl = *(const uint2*)&sW1F[8192 + idx];
                mma_bf16(tacc[nt], &hH[kt*4], bh.x, bh.y);
                mma_bf16(tacc[nt], &hH[kt*4], bl.x, bl.y);
                mma_bf16(tacc[nt], &hL[kt*4], bh.x, bh.y);
            }
        }
        // epilogue: t = relu(tacc + ba1) -> A2 frags
        u32 tH[16], tL[16];
#pragma unroll
        for (int nt = 0; nt < 8; nt++) {
            int c0 = ch*64 + nt*8 + tig*2;
            float b0 = sBa1[c0], b1 = sBa1[c0+1];
            float t0 = fmaxf(tacc[nt][0] + b0, 0.f);
            float t1 = fmaxf(tacc[nt][1] + b1, 0.f);
            float t2 = fmaxf(tacc[nt][2] + b0, 0.f);
            float t3 = fmaxf(tacc[nt][3] + b1, 0.f);
            int fr = (nt >> 1)*4 + (nt & 1)*2;
            tH[fr]   = pack_hi(t0, t1);  tL[fr]   = pack_lo(t0, t1);
            tH[fr+1] = pack_hi(t2, t3);  tL[fr+1] = pack_lo(t2, t3);
        }
        // MMA2 partial over this chunk's K
#pragma unroll
        for (int kl = 0; kl < 4; kl++) {
            int kt2 = ch*4 + kl;
#pragma unroll
            for (int nt = 0; nt < 8; nt++) {
                int idx = ((kt2*8 + nt)*32 + lane)*2;
                uint2 bh = *(const uint2*)&sW2F[idx];
                uint2 bl = *(const uint2*)&sW2F[8192 + idx];
                mma_bf16(sim[nt], &tH[kl*4], bh.x, bh.y);
                mma_bf16(sim[nt], &tH[kl*4], bl.x, bl.y);
                mma_bf16(sim[nt], &tL[kl*4], bh.x, bh.y);
            }
        }
    }

    // ---- sim bias + softmax (rows A and B) ----
#pragma unroll
    for (int nt = 0; nt < 8; nt++) {
        int c0 = nt*8 + tig*2;
        float b0 = sBa2[c0], b1 = sBa2[c0+1];
        sim[nt][0] += b0; sim[nt][1] += b1;
        sim[nt][2] += b0; sim[nt][3] += b1;
    }
    {
        float mxA = -3.4e38f, mxB = -3.4e38f;
#pragma unroll
        for (int nt = 0; nt < 8; nt++) {
            mxA = fmaxf(mxA, fmaxf(sim[nt][0], sim[nt][1]));
            mxB = fmaxf(mxB, fmaxf(sim[nt][2], sim[nt][3]));
        }
        mxA = fmaxf(mxA, __shfl_xor_sync(0xffffffffu, mxA, 1));
        mxA = fmaxf(mxA, __shfl_xor_sync(0xffffffffu, mxA, 2));
        mxB = fmaxf(mxB, __shfl_xor_sync(0xffffffffu, mxB, 1));
        mxB = fmaxf(mxB, __shfl_xor_sync(0xffffffffu, mxB, 2));
        float sA = 0.f, sB = 0.f;
#pragma unroll
        for (int nt = 0; nt < 8; nt++) {
            sim[nt][0] = __expf(sim[nt][0] - mxA); sA += sim[nt][0];
            sim[nt][1] = __expf(sim[nt][1] - mxA); sA += sim[nt][1];
            sim[nt][2] = __expf(sim[nt][2] - mxB); sB += sim[nt][2];
            sim[nt][3] = __expf(sim[nt][3] - mxB); sB += sim[nt][3];
        }
        sA += __shfl_xor_sync(0xffffffffu, sA, 1);
        sA += __shfl_xor_sync(0xffffffffu, sA, 2);
        sB += __shfl_xor_sync(0xffffffffu, sB, 1);
        sB += __shfl_xor_sync(0xffffffffu, sB, 2);
        float iA = 1.f / sA, iB = 1.f / sB;
#pragma unroll
        for (int nt = 0; nt < 8; nt++) {
            sim[nt][0] *= iA; sim[nt][1] *= iA;
            sim[nt][2] *= iB; sim[nt][3] *= iB;
        }
    }

    // ---- channel norm over 16 neighbors + aggregate ----
#pragma unroll
    for (int nt = 0; nt < 8; nt++) {
#pragma unroll
        for (int p = 0; p < 2; p++) {
            float a0 = sim[nt][p], a1 = sim[nt][2+p];
            float s2 = a0*a0 + a1*a1;
            float dv = a0*vnr[nt][p] + a1*vnr[nt][2+p];
            s2 += __shfl_xor_sync(0xffffffffu, s2, 4);
            s2 += __shfl_xor_sync(0xffffffffu, s2, 8);
            s2 += __shfl_xor_sync(0xffffffffu, s2, 16);
            dv += __shfl_xor_sync(0xffffffffu, dv, 4);
            dv += __shfl_xor_sync(0xffffffffu, dv, 8);
            dv += __shfl_xor_sync(0xffffffffu, dv, 16);
            if (g == 0)
                sAgg[mt*64 + nt*8 + tig*2 + p] = dv / fmaxf(sqrtf(s2), 1e-12f);
        }
    }
    __syncthreads();

    // ---- P7: out = agg @ w_out + b_out ----
    if (tid < 256) {
        float acc[PPB];
        float bb = b_out[tid];
#pragma unroll
        for (int p = 0; p < PPB; p++) acc[p] = bb;
        for (int k = 0; k < 64; k++) {
            float w = w_out[k*256 + tid];
#pragma unroll
            for (int p = 0; p < PPB; p++)
                acc[p] += sAgg[p*64 + k] * w;
        }
#pragma unroll
        for (int p = 0; p < PPB; p++)
            if (gp0 + p < NPTS_)
                out[(gp0 + p)*256 + tid] = acc[p];
    }
}

// ---------------------------------------------------------------------------
extern "C" void kernel_launch(void* const* d_in, const int* in_sizes, int n_in,
                              void* d_out, int out_size)
{
    const float* x      = (const float*)d_in[0];
    const float* pos    = (const float*)d_in[1];
    const float* w_qkv  = (const float*)d_in[2];
    const float* w_pos1 = (const float*)d_in[3];
    const float* b_pos1 = (const float*)d_in[4];
    const float* w_pos2 = (const float*)d_in[5];
    const float* b_pos2 = (const float*)d_in[6];
    const float* w_att1 = (const float*)d_in[7];
    const float* b_att1 = (const float*)d_in[8];
    const float* w_att2 = (const float*)d_in[9];
    const float* b_att2 = (const float*)d_in[10];
    const float* w_out  = (const float*)d_in[11];
    const float* b_out  = (const float*)d_in[12];
    float* out = (float*)d_out;

    (void)in_sizes; (void)n_in; (void)out_size;

    cudaFuncSetAttribute(fused_kernel,
                         cudaFuncAttributeMaxDynamicSharedMemorySize, SMEM_FUSED_BYTES);
    const int smem_knn = (6144 + 4096 + 4096) * 4;
    cudaFuncSetAttribute(knn_kernel,
                         cudaFuncAttributeMaxDynamicSharedMemorySize, smem_knn);

    prep_kernel<<<336, 256>>>(w_qkv, w_att1, w_att2, w_pos2);
    xfrag_kernel<<<8192, 256>>>(x);
    qkv_mma_kernel<<<256, 128>>>();
    knn_kernel<<<256, 256, smem_knn>>>(pos);
    fused_kernel<<<(NPTS_ + PPB - 1)/PPB, 384, SMEM_FUSED_BYTES>>>(
        pos, w_pos1, b_pos1, b_pos2, b_att1, b_att2, w_out, b_out, out);
}

// round 16
// speedup vs baseline: 1.2173x; 1.0076x over previous
#include <cuda_runtime.h>
#include <cuda_bf16.h>

#define B_    8
#define N_    2048
#define EMB_  256
#define KNN_  16
#define NPTS_ (B_*N_)

typedef unsigned long long ull;
typedef unsigned int u32;

// bf16 hi/lo split packers (lower col -> low 16 bits)
__device__ __forceinline__ u32 pack_hi(float v0, float v1) {
    __nv_bfloat162 h = __floats2bfloat162_rn(v0, v1);
    return *(u32*)&h;
}
__device__ __forceinline__ u32 pack_lo(float v0, float v1) {
    __nv_bfloat16 h0 = __float2bfloat16(v0), h1 = __float2bfloat16(v1);
    __nv_bfloat162 l = __floats2bfloat162_rn(v0 - __bfloat162float(h0),
                                             v1 - __bfloat162float(h1));
    return *(u32*)&l;
}

// m16n8k16 bf16 mma, f32 accum
__device__ __forceinline__ void mma_bf16(float d[4], const u32 a[4], u32 b0, u32 b1) {
    asm("mma.sync.aligned.m16n8k16.row.col.f32.bf16.bf16.f32 "
        "{%0,%1,%2,%3}, {%4,%5,%6,%7}, {%8,%9}, {%0,%1,%2,%3};"
        : "+f"(d[0]), "+f"(d[1]), "+f"(d[2]), "+f"(d[3])
        : "r"(a[0]), "r"(a[1]), "r"(a[2]), "r"(a[3]), "r"(b0), "r"(b1));
}

// ---- Scratch (device globals) ----
__device__ float g_qmk[NPTS_*64];
__device__ float g_v  [NPTS_*64];
__device__ int   g_idx[NPTS_*KNN_];
// B-fragment-ordered weights, bf16 hi half then lo half:
__device__ __align__(16) u32 g_wqf[49152];        // w_qkv  [kt16][nt24][lane][b2] x2
__device__ __align__(16) u32 g_w1f[16384];        // w_att1 [kt4][nt32][lane][b2] x2
__device__ __align__(16) u32 g_w2f[16384];        // w_att2 [kt16][nt8][lane][b2] x2
__device__ __align__(16) u32 g_wpf[4096];         // w_pos2 [kt4][nt8][lane][b2] x2
// x as A-fragments (hi/lo): [mtile1024][kt16][lane32][r4]
__device__ __align__(16) u32 g_xfh[2097152];
__device__ __align__(16) u32 g_xfl[2097152];

// ---------------------------------------------------------------------------
__global__ __launch_bounds__(256) void prep_kernel(
    const float* __restrict__ wq, const float* __restrict__ w1,
    const float* __restrict__ w2, const float* __restrict__ wp)
{
    int i = blockIdx.x*256 + threadIdx.x;
    if (i < 49152) {
        int half = (i >= 24576);
        int j2 = half ? i - 24576 : i;
        int b = j2 & 1, lane = (j2 >> 1) & 31;
        int ktnt = j2 >> 6;            // 0..383
        int nt = ktnt % 24, kt = ktnt / 24;
        int tig = lane & 3, g = lane >> 2;
        int k0 = kt*16 + tig*2 + 8*b, n = nt*8 + g;
        float v0 = wq[k0*192 + n], v1 = wq[(k0+1)*192 + n];
        g_wqf[i] = half ? pack_lo(v0, v1) : pack_hi(v0, v1);
    } else if (i < 53248) {
        int j = i - 49152;               // wp2 frags, 4096 u32
        int half = j >> 11, j2 = j & 2047;
        int b = j2 & 1, lane = (j2 >> 1) & 31, nt = (j2 >> 6) & 7, kt = j2 >> 9;
        int tig = lane & 3, g = lane >> 2;
        int k0 = kt*16 + tig*2 + 8*b, n = nt*8 + g;
        float v0 = wp[k0*64 + n], v1 = wp[(k0+1)*64 + n];
        g_wpf[j] = half ? pack_lo(v0, v1) : pack_hi(v0, v1);
    } else if (i < 69632) {
        int j = i - 53248;               // w1 frags, 16384 u32
        int half = j >> 13, j2 = j & 8191;
        int b = j2 & 1, lane = (j2 >> 1) & 31, nt = (j2 >> 6) & 31, kt = j2 >> 11;
        int tig = lane & 3, g = lane >> 2;
        int k0 = kt*16 + tig*2 + 8*b, n = nt*8 + g;
        float v0 = w1[k0*256 + n], v1 = w1[(k0+1)*256 + n];
        g_w1f[j] = half ? pack_lo(v0, v1) : pack_hi(v0, v1);
    } else if (i < 86016) {
        int j = i - 69632;               // w2 frags, 16384 u32
        int half = j >> 13, j2 = j & 8191;
        int b = j2 & 1, lane = (j2 >> 1) & 31, nt = (j2 >> 6) & 7, kt = j2 >> 9;
        int tig = lane & 3, g = lane >> 2;
        int k0 = kt*16 + tig*2 + 8*b, n = nt*8 + g;
        float v0 = w2[k0*64 + n], v1 = w2[(k0+1)*64 + n];
        g_w2f[j] = half ? pack_lo(v0, v1) : pack_hi(v0, v1);
    }
}

// ---------------------------------------------------------------------------
// xfrag: convert x -> bf16 hi/lo A-fragments (coalesced).
// ---------------------------------------------------------------------------
__global__ __launch_bounds__(256) void xfrag_kernel(const float* __restrict__ x)
{
    int j = blockIdx.x*256 + threadIdx.x;     // < 2097152
    int r = j & 3;
    int lane = (j >> 2) & 31;
    int kt = (j >> 7) & 15;
    int m  = j >> 11;
    int g = lane >> 2, tig = lane & 3;
    int row = m*16 + (r & 1)*8 + g;
    int k   = kt*16 + (r >> 1)*8 + tig*2;
    float2 xv = *(const float2*)&x[row*256 + k];
    g_xfh[j] = pack_hi(xv.x, xv.y);
    g_xfl[j] = pack_lo(xv.x, xv.y);
}

// ---------------------------------------------------------------------------
// qkv via mma: 4 warps/block, warp = one 16-row m-tile; grid 256.
// ---------------------------------------------------------------------------
__global__ __launch_bounds__(128) void qkv_mma_kernel()
{
    int wid = threadIdx.x >> 5, lane = threadIdx.x & 31;
    int mt = blockIdx.x*4 + wid;              // 0..1023
    int g = lane >> 2, tig = lane & 3;

    float acc[24][4];
#pragma unroll
    for (int nt = 0; nt < 24; nt++)
#pragma unroll
        for (int r = 0; r < 4; r++) acc[nt][r] = 0.f;

#pragma unroll 4
    for (int kt = 0; kt < 16; kt++) {
        int abase = ((mt*16 + kt)*32 + lane)*4;
        uint4 ah4 = *(const uint4*)&g_xfh[abase];
        uint4 al4 = *(const uint4*)&g_xfl[abase];
        u32 ah[4] = {ah4.x, ah4.y, ah4.z, ah4.w};
        u32 al[4] = {al4.x, al4.y, al4.z, al4.w};
#pragma unroll
        for (int nt = 0; nt < 24; nt++) {
            int idx = ((kt*24 + nt)*32 + lane)*2;
            uint2 bh = *(const uint2*)&g_wqf[idx];
            uint2 bl = *(const uint2*)&g_wqf[24576 + idx];
            mma_bf16(acc[nt], ah, bh.x, bh.y);
            mma_bf16(acc[nt], ah, bl.x, bl.y);
            mma_bf16(acc[nt], al, bh.x, bh.y);
        }
    }

    int row0 = mt*16 + g;
#pragma unroll
    for (int nt = 0; nt < 8; nt++) {
        int c = nt*8 + tig*2;
        float2 qa = make_float2(acc[nt][0] - acc[nt+8][0], acc[nt][1] - acc[nt+8][1]);
        float2 qb = make_float2(acc[nt][2] - acc[nt+8][2], acc[nt][3] - acc[nt+8][3]);
        *(float2*)&g_qmk[row0*64 + c]     = qa;
        *(float2*)&g_qmk[(row0+8)*64 + c] = qb;
        *(float2*)&g_v[row0*64 + c]     = make_float2(acc[nt+16][0], acc[nt+16][1]);
        *(float2*)&g_v[(row0+8)*64 + c] = make_float2(acc[nt+16][2], acc[nt+16][3]);
    }
}

// ---------------------------------------------------------------------------
// kNN v6: 256 blocks x 256 threads; 64 q/block, 4 shards x 512 candidates.
// Pass 1 keeps TWO independent sorted top-16 lists (even/odd candidates)
// for 2x ILP on the min/max cascades; 16-smallest of the union recovered
// via the bitonic lower-half property. thr+eq rescan, sort, 4-way merge.
// ---------------------------------------------------------------------------
__global__ __launch_bounds__(256) void knn_kernel(const float* __restrict__ pos)
{
    extern __shared__ float ksm[];
    float* sx = ksm;                  // 2048
    float* sy = ksm + 2048;           // 2048
    float* sz = ksm + 4096;           // 2048
    float* sd = ksm + 6144;           // 4096
    int*   si = (int*)(ksm + 10240);  // 4096

    int batch = blockIdx.x >> 5;      // 8 batches
    int chunk = blockIdx.x & 31;      // 32 chunks of 64 queries
    const float* pb = pos + batch*N_*3;
    for (int e = threadIdx.x; e < N_*3; e += 256) {
        float v = pb[e];
        int j = e / 3, c = e - j*3;
        (c == 0 ? sx : c == 1 ? sy : sz)[j] = v;
    }
    __syncthreads();

    int q = threadIdx.x >> 2;          // 0..63 local query
    int s = threadIdx.x & 3;           // shard 0..3
    int qi = chunk*64 + q;
    float px = sx[qi], py = sy[qi], pz = sz[qi];

    const float2* sx2 = (const float2*)sx;
    const float2* sy2 = (const float2*)sy;
    const float2* sz2 = (const float2*)sz;
    int jj0 = s * 256;                 // 256 float2 pairs = 512 candidates

    // ---- Pass 1: two independent sorted top-16 lists (2x ILP) ----
    float bd0[KNN_], bd1[KNN_];
#pragma unroll
    for (int t = 0; t < KNN_; t++) { bd0[t] = 3.4e38f; bd1[t] = 3.4e38f; }

    for (int jj = jj0; jj < jj0 + 256; jj++) {
        float2 X = sx2[jj], Y = sy2[jj], Z = sz2[jj];
        float dxa = X.x - px, dya = Y.x - py, dza = Z.x - pz;
        float dxb = X.y - px, dyb = Y.y - py, dzb = Z.y - pz;
        float da = fmaf(dxa, dxa, fmaf(dya, dya, dza*dza));
        float db = fmaf(dxb, dxb, fmaf(dyb, dyb, dzb*dzb));
        float c0 = da, c1 = db;        // two independent cascades
#pragma unroll
        for (int t = 0; t < KNN_; t++) {
            float lo0 = fminf(bd0[t], c0);
            float lo1 = fminf(bd1[t], c1);
            c0 = fmaxf(bd0[t], c0);
            c1 = fmaxf(bd1[t], c1);
            bd0[t] = lo0;
            bd1[t] = lo1;
        }
    }

    // ---- 16 smallest of union via bitonic lower half; thr + eq-count ----
    float lower[KNN_];
#pragma unroll
    for (int t = 0; t < KNN_; t++)
        lower[t] = fminf(bd0[t], bd1[KNN_-1-t]);
    float thr = lower[0];
#pragma unroll
    for (int t = 1; t < KNN_; t++) thr = fmaxf(thr, lower[t]);
    int e_eq = 0;
#pragma unroll
    for (int t = 0; t < KNN_; t++) e_eq += (lower[t] == thr) ? 1 : 0;

    // ---- Pass 2: rescan, emit exactly 16 (d, idx) into smem ----
    int lb = (q*4 + s)*16;
    int cnt = 0, eq_taken = 0;
    for (int jj = jj0; jj < jj0 + 256; jj++) {
        float2 X = sx2[jj], Y = sy2[jj], Z = sz2[jj];
        float dxa = X.x - px, dya = Y.x - py, dza = Z.x - pz;
        float dxb = X.y - px, dyb = Y.y - py, dzb = Z.y - pz;
        float da = fmaf(dxa, dxa, fmaf(dya, dya, dza*dza));
        float db = fmaf(dxb, dxb, fmaf(dyb, dyb, dzb*dzb));
        if (da <= thr) {
            bool take = (da < thr) || (eq_taken < e_eq);
            if (take) {
                if (!(da < thr)) eq_taken++;
                sd[lb + cnt] = da;
                si[lb + cnt] = 2*jj;
                cnt++;
            }
        }
        if (db <= thr) {
            bool take = (db < thr) || (eq_taken < e_eq);
            if (take) {
                if (!(db < thr)) eq_taken++;
                sd[lb + cnt] = db;
                si[lb + cnt] = 2*jj + 1;
                cnt++;
            }
        }
    }

    // ---- per-thread sort of its 16 (d, i) ----
    {
        float od[KNN_]; int oi[KNN_];
#pragma unroll
        for (int t = 0; t < KNN_; t++) { od[t] = 3.4e38f; oi[t] = 0; }
#pragma unroll
        for (int u = 0; u < KNN_; u++) {
            float cd = sd[lb + u]; int ci = si[lb + u];
#pragma unroll
            for (int t = 0; t < KNN_; t++) {
                if (cd < od[t]) {
                    float td = od[t]; od[t] = cd; cd = td;
                    int   ti = oi[t]; oi[t] = ci; ci = ti;
                }
            }
        }
#pragma unroll
        for (int t = 0; t < KNN_; t++) { sd[lb+t] = od[t]; si[lb+t] = oi[t]; }
    }
    __syncthreads();

    // ---- 4-way merge (threads 0..63) ----
    if (threadIdx.x < 64) {
        int qq = threadIdx.x;
        int p[4] = {0,0,0,0};
        int base = qq*64;
        int obase = (batch*N_ + chunk*64 + qq)*KNN_;
#pragma unroll
        for (int t = 0; t < KNN_; t++) {
            float best = sd[base + p[0]]; int bsel = 0;
            float c1 = sd[base + 16 + p[1]];
            if (c1 < best) { best = c1; bsel = 1; }
            float c2 = sd[base + 32 + p[2]];
            if (c2 < best) { best = c2; bsel = 2; }
            float c3 = sd[base + 48 + p[3]];
            if (c3 < best) { best = c3; bsel = 3; }
            g_idx[obase + t] = batch*N_ + si[base + bsel*16 + p[bsel]];
            p[bsel]++;
        }
    }
}

// ---------------------------------------------------------------------------
// Fused mma.sync kernel: 12 points/block, 12 warps (warp = point m-tile).
// ---------------------------------------------------------------------------
#define PPB 12
#define SMEM_FUSED_BYTES 156928

__global__ __launch_bounds__(384) void fused_kernel(
    const float* __restrict__ pos,
    const float* __restrict__ w_pos1, const float* __restrict__ b_pos1,
    const float* __restrict__ b_pos2,
    const float* __restrict__ b_att1, const float* __restrict__ b_att2,
    const float* __restrict__ w_out,  const float* __restrict__ b_out,
    float* __restrict__ out)
{
    extern __shared__ u32 smu[];
    u32* sW1F = smu;                 // 16384
    u32* sW2F = smu + 16384;         // 16384
    u32* sWPF = smu + 32768;         // 4096
    float* sF   = (float*)(smu + 36864);
    float* sRel = sF;                // 768 (192 x 4)
    float* sWP1 = sF + 768;          // 192
    float* sBp1 = sF + 960;          // 64
    float* sBp2 = sF + 1024;         // 64
    float* sBa1 = sF + 1088;         // 256
    float* sBa2 = sF + 1344;         // 64
    float* sAgg = sF + 1408;         // 768
    int*   sNbr = (int*)(sF + 2176); // 192

    const int tid  = threadIdx.x;
    const int wid  = tid >> 5;
    const int lane = tid & 31;
    const int gp0  = blockIdx.x * PPB;

    // ---- staging ----
    {
        const uint4* s1 = (const uint4*)g_w1f;  uint4* d1 = (uint4*)sW1F;
        const uint4* s2 = (const uint4*)g_w2f;  uint4* d2 = (uint4*)sW2F;
        for (int i = tid; i < 4096; i += 384) { d1[i] = s1[i]; d2[i] = s2[i]; }
        const uint4* s3 = (const uint4*)g_wpf;  uint4* d3 = (uint4*)sWPF;
        for (int i = tid; i < 1024; i += 384) d3[i] = s3[i];
    }
    if (tid < 192) sWP1[tid] = w_pos1[tid];
    if (tid < 64) {
        sBp1[tid] = b_pos1[tid];
        sBp2[tid] = b_pos2[tid];
        sBa2[tid] = b_att2[tid];
    }
    if (tid < 256) sBa1[tid] = b_att1[tid];
    if (tid < 16*PPB) {
        int gp = gp0 + (tid >> 4);
        if (gp >= NPTS_) gp = NPTS_ - 1;           // clamp (tail block)
        int nbr = g_idx[gp*KNN_ + (tid & 15)];
        sNbr[tid] = nbr;
        sRel[tid*4+0] = pos[nbr*3+0] - pos[gp*3+0];
        sRel[tid*4+1] = pos[nbr*3+1] - pos[gp*3+1];
        sRel[tid*4+2] = pos[nbr*3+2] - pos[gp*3+2];
    }
    __syncthreads();

    const int mt  = wid;            // point / m-tile (0..11)
    const int g   = lane >> 2;
    const int tig = lane & 3;
    const int prA = mt*16 + g;      // pair-row A
    const int prB = prA + 8;        // pair-row B

    // ---- P1: mid = relu(rel @ wp1 + bp1) -> A-frags (regs) ----
    u32 midH[16], midL[16];
    {
        float rA0 = sRel[prA*4+0], rA1 = sRel[prA*4+1], rA2 = sRel[prA*4+2];
        float rB0 = sRel[prB*4+0], rB1 = sRel[prB*4+1], rB2 = sRel[prB*4+2];
#pragma unroll
        for (int kt = 0; kt < 4; kt++)
#pragma unroll
            for (int cb = 0; cb < 2; cb++) {
                int c0 = kt*16 + cb*8 + tig*2;
                float wx0 = sWP1[c0],   wy0 = sWP1[64+c0],   wz0 = sWP1[128+c0];
                float wx1 = sWP1[c0+1], wy1 = sWP1[64+c0+1], wz1 = sWP1[128+c0+1];
                float bb0 = sBp1[c0], bb1 = sBp1[c0+1];
                float a0 = fmaxf(rA0*wx0 + rA1*wy0 + rA2*wz0 + bb0, 0.f);
                float a1 = fmaxf(rA0*wx1 + rA1*wy1 + rA2*wz1 + bb1, 0.f);
                float b0 = fmaxf(rB0*wx0 + rB1*wy0 + rB2*wz0 + bb0, 0.f);
                float b1 = fmaxf(rB0*wx1 + rB1*wy1 + rB2*wz1 + bb1, 0.f);
                int r = kt*4 + cb*2;
                midH[r]   = pack_hi(a0, a1);  midL[r]   = pack_lo(a0, a1);
                midH[r+1] = pack_hi(b0, b1);  midL[r+1] = pack_lo(b0, b1);
            }
    }

    // ---- P2: rpe = mid @ wp2 (mma, split x3) ----
    float rpe[8][4];
#pragma unroll
    for (int nt = 0; nt < 8; nt++)
#pragma unroll
        for (int r = 0; r < 4; r++) rpe[nt][r] = 0.f;
#pragma unroll
    for (int kt = 0; kt < 4; kt++) {
#pragma unroll
        for (int nt = 0; nt < 8; nt++) {
            int idx = ((kt*8 + nt)*32 + lane)*2;
            uint2 bh = *(const uint2*)&sWPF[idx];
            uint2 bl = *(const uint2*)&sWPF[2048 + idx];
            mma_bf16(rpe[nt], &midH[kt*4], bh.x, bh.y);
            mma_bf16(rpe[nt], &midH[kt*4], bl.x, bl.y);
            mma_bf16(rpe[nt], &midL[kt*4], bh.x, bh.y);
        }
    }

    // ---- P2 epilogue: h frags (regs) + vn (regs) ----
    u32 hH[16], hL[16];
    float vnr[8][4];
    {
        int nA = sNbr[prA], nB = sNbr[prB];
#pragma unroll
        for (int nt = 0; nt < 8; nt++) {
            int c0 = nt*8 + tig*2;
            float b0 = sBp2[c0], b1 = sBp2[c0+1];
            float2 qA = *(const float2*)&g_qmk[nA*64 + c0];
            float2 qB = *(const float2*)&g_qmk[nB*64 + c0];
            float2 vA = *(const float2*)&g_v[nA*64 + c0];
            float2 vB = *(const float2*)&g_v[nB*64 + c0];
            float r0 = rpe[nt][0] + b0, r1 = rpe[nt][1] + b1;
            float r2 = rpe[nt][2] + b0, r3 = rpe[nt][3] + b1;
            vnr[nt][0] = vA.x + r0;  vnr[nt][1] = vA.y + r1;
            vnr[nt][2] = vB.x + r2;  vnr[nt][3] = vB.y + r3;
            int fr = (nt >> 1)*4 + (nt & 1)*2;
            float hA0 = qA.x + r0, hA1 = qA.y + r1;
            float hB0 = qB.x + r2, hB1 = qB.y + r3;
            hH[fr]   = pack_hi(hA0, hA1);  hL[fr]   = pack_lo(hA0, hA1);
            hH[fr+1] = pack_hi(hB0, hB1);  hL[fr+1] = pack_lo(hB0, hB1);
        }
    }

    // ---- MMA1 + epilogue + MMA2, chunked over t columns ----
    float sim[8][4];
#pragma unroll
    for (int nt = 0; nt < 8; nt++)
#pragma unroll
        for (int r = 0; r < 4; r++) sim[nt][r] = 0.f;

#pragma unroll
    for (int ch = 0; ch < 4; ch++) {
        float tacc[8][4];
#pragma unroll
        for (int nt = 0; nt < 8; nt++)
#pragma unroll
            for (int r = 0; r < 4; r++) tacc[nt][r] = 0.f;
#pragma unroll
        for (int kt = 0; kt < 4; kt++) {
#pragma unroll
            for (int nt = 0; nt < 8; nt++) {
                int idx = ((kt*32 + ch*8 + nt)*32 + lane)*2;
                uint2 bh = *(const uint2*)&sW1F[idx];
                uint2 bl = *(const uint2*)&sW1F[8192 + idx];
                mma_bf16(tacc[nt], &hH[kt*4], bh.x, bh.y);
                mma_bf16(tacc[nt], &hH[kt*4], bl.x, bl.y);
                mma_bf16(tacc[nt], &hL[kt*4], bh.x, bh.y);
            }
        }
        // epilogue: t = relu(tacc + ba1) -> A2 frags
        u32 tH[16], tL[16];
#pragma unroll
        for (int nt = 0; nt < 8; nt++) {
            int c0 = ch*64 + nt*8 + tig*2;
            float b0 = sBa1[c0], b1 = sBa1[c0+1];
            float t0 = fmaxf(tacc[nt][0] + b0, 0.f);
            float t1 = fmaxf(tacc[nt][1] + b1, 0.f);
            float t2 = fmaxf(tacc[nt][2] + b0, 0.f);
            float t3 = fmaxf(tacc[nt][3] + b1, 0.f);
            int fr = (nt >> 1)*4 + (nt & 1)*2;
            tH[fr]   = pack_hi(t0, t1);  tL[fr]   = pack_lo(t0, t1);
            tH[fr+1] = pack_hi(t2, t3);  tL[fr+1] = pack_lo(t2, t3);
        }
        // MMA2 partial over this chunk's K
#pragma unroll
        for (int kl = 0; kl < 4; kl++) {
            int kt2 = ch*4 + kl;
#pragma unroll
            for (int nt = 0; nt < 8; nt++) {
                int idx = ((kt2*8 + nt)*32 + lane)*2;
                uint2 bh = *(const uint2*)&sW2F[idx];
                uint2 bl = *(const uint2*)&sW2F[8192 + idx];
                mma_bf16(sim[nt], &tH[kl*4], bh.x, bh.y);
                mma_bf16(sim[nt], &tH[kl*4], bl.x, bl.y);
                mma_bf16(sim[nt], &tL[kl*4], bh.x, bh.y);
            }
        }
    }

    // ---- sim bias + softmax (rows A and B) ----
#pragma unroll
    for (int nt = 0; nt < 8; nt++) {
        int c0 = nt*8 + tig*2;
        float b0 = sBa2[c0], b1 = sBa2[c0+1];
        sim[nt][0] += b0; sim[nt][1] += b1;
        sim[nt][2] += b0; sim[nt][3] += b1;
    }
    {
        float mxA = -3.4e38f, mxB = -3.4e38f;
#pragma unroll
        for (int nt = 0; nt < 8; nt++) {
            mxA = fmaxf(mxA, fmaxf(sim[nt][0], sim[nt][1]));
            mxB = fmaxf(mxB, fmaxf(sim[nt][2], sim[nt][3]));
        }
        mxA = fmaxf(mxA, __shfl_xor_sync(0xffffffffu, mxA, 1));
        mxA = fmaxf(mxA, __shfl_xor_sync(0xffffffffu, mxA, 2));
        mxB = fmaxf(mxB, __shfl_xor_sync(0xffffffffu, mxB, 1));
        mxB = fmaxf(mxB, __shfl_xor_sync(0xffffffffu, mxB, 2));
        float sA = 0.f, sB = 0.f;
#pragma unroll
        for (int nt = 0; nt < 8; nt++) {
            sim[nt][0] = __expf(sim[nt][0] - mxA); sA += sim[nt][0];
            sim[nt][1] = __expf(sim[nt][1] - mxA); sA += sim[nt][1];
            sim[nt][2] = __expf(sim[nt][2] - mxB); sB += sim[nt][2];
            sim[nt][3] = __expf(sim[nt][3] - mxB); sB += sim[nt][3];
        }
        sA += __shfl_xor_sync(0xffffffffu, sA, 1);
        sA += __shfl_xor_sync(0xffffffffu, sA, 2);
        sB += __shfl_xor_sync(0xffffffffu, sB, 1);
        sB += __shfl_xor_sync(0xffffffffu, sB, 2);
        float iA = 1.f / sA, iB = 1.f / sB;
#pragma unroll
        for (int nt = 0; nt < 8; nt++) {
            sim[nt][0] *= iA; sim[nt][1] *= iA;
            sim[nt][2] *= iB; sim[nt][3] *= iB;
        }
    }

    // ---- channel norm over 16 neighbors + aggregate ----
#pragma unroll
    for (int nt = 0; nt < 8; nt++) {
#pragma unroll
        for (int p = 0; p < 2; p++) {
            float a0 = sim[nt][p], a1 = sim[nt][2+p];
            float s2 = a0*a0 + a1*a1;
            float dv = a0*vnr[nt][p] + a1*vnr[nt][2+p];
            s2 += __shfl_xor_sync(0xffffffffu, s2, 4);
            s2 += __shfl_xor_sync(0xffffffffu, s2, 8);
            s2 += __shfl_xor_sync(0xffffffffu, s2, 16);
            dv += __shfl_xor_sync(0xffffffffu, dv, 4);
            dv += __shfl_xor_sync(0xffffffffu, dv, 8);
            dv += __shfl_xor_sync(0xffffffffu, dv, 16);
            if (g == 0)
                sAgg[mt*64 + nt*8 + tig*2 + p] = dv / fmaxf(sqrtf(s2), 1e-12f);
        }
    }
    __syncthreads();

    // ---- P7: out = agg @ w_out + b_out ----
    if (tid < 256) {
        float acc[PPB];
        float bb = b_out[tid];
#pragma unroll
        for (int p = 0; p < PPB; p++) acc[p] = bb;
        for (int k = 0; k < 64; k++) {
            float w = w_out[k*256 + tid];
#pragma unroll
            for (int p = 0; p < PPB; p++)
                acc[p] += sAgg[p*64 + k] * w;
        }
#pragma unroll
        for (int p = 0; p < PPB; p++)
            if (gp0 + p < NPTS_)
                out[(gp0 + p)*256 + tid] = acc[p];
    }
}

// ---------------------------------------------------------------------------
extern "C" void kernel_launch(void* const* d_in, const int* in_sizes, int n_in,
                              void* d_out, int out_size)
{
    const float* x      = (const float*)d_in[0];
    const float* pos    = (const float*)d_in[1];
    const float* w_qkv  = (const float*)d_in[2];
    const float* w_pos1 = (const float*)d_in[3];
    const float* b_pos1 = (const float*)d_in[4];
    const float* w_pos2 = (const float*)d_in[5];
    const float* b_pos2 = (const float*)d_in[6];
    const float* w_att1 = (const float*)d_in[7];
    const float* b_att1 = (const float*)d_in[8];
    const float* w_att2 = (const float*)d_in[9];
    const float* b_att2 = (const float*)d_in[10];
    const float* w_out  = (const float*)d_in[11];
    const float* b_out  = (const float*)d_in[12];
    float* out = (float*)d_out;

    (void)in_sizes; (void)n_in; (void)out_size;

    cudaFuncSetAttribute(fused_kernel,
                         cudaFuncAttributeMaxDynamicSharedMemorySize, SMEM_FUSED_BYTES);
    const int smem_knn = (6144 + 4096 + 4096) * 4;
    cudaFuncSetAttribute(knn_kernel,
                         cudaFuncAttributeMaxDynamicSharedMemorySize, smem_knn);

    prep_kernel<<<336, 256>>>(w_qkv, w_att1, w_att2, w_pos2);
    xfrag_kernel<<<8192, 256>>>(x);
    qkv_mma_kernel<<<256, 128>>>();
    knn_kernel<<<256, 256, smem_knn>>>(pos);
    fused_kernel<<<(NPTS_ + PPB - 1)/PPB, 384, SMEM_FUSED_BYTES>>>(
        pos, w_pos1, b_pos1, b_pos2, b_att1, b_att2, w_out, b_out, out);
}